// round 5
// baseline (speedup 1.0000x reference)
#include <cuda_runtime.h>
#include <cuda_bf16.h>
#include <cuda_fp16.h>
#include <cstdint>

// Problem constants
#define NN 20000
#define TT 8
#define FIN 64
#define HEADS 4
#define FILT 32
#define HID 128
#define EE 320000
#define ETOT 340000      // E + N self loops
#define MROWS 160000     // N*T

// ---------------- device scratch ----------------
__device__ __half        g_h16[(size_t)MROWS * HID];  // post-GEMM h (fp16, for gathers)
__device__ __nv_bfloat16 g_ah[(size_t)MROWS * HID];   // agg output hi (GEMM A)
__device__ __nv_bfloat16 g_al[(size_t)MROWS * HID];   // agg output lo
__device__ __nv_bfloat16 g_xh[(size_t)MROWS * FIN];   // x split hi (permuted)
__device__ __nv_bfloat16 g_xl[(size_t)MROWS * FIN];
__device__ __nv_bfloat16 g_w1h[HID * FIN],  g_w1l[HID * FIN];
__device__ __nv_bfloat16 g_w2h[HID * HID],  g_w2l[HID * HID];
__device__ __nv_bfloat16 g_w3h[FILT * HID], g_w3l[FILT * HID];
__device__ float  g_es[(size_t)MROWS * HEADS];
__device__ float  g_ed[(size_t)MROWS * HEADS];
__device__ int    g_deg[NN];
__device__ int    g_ticket;
__device__ int    g_rowptr[NN + 1];
__device__ int    g_cursor[NN];
__device__ int    g_csrc[ETOT];

// ---------------- split helper ----------------
__device__ __forceinline__ void split2(float v, __nv_bfloat16& hi, __nv_bfloat16& lo) {
    hi = __float2bfloat16(v);
    lo = __float2bfloat16(v - __bfloat162float(hi));
}

// ---------------- prep: zero deg/ticket + split weights + split/permute x --
__global__ __launch_bounds__(256) void prep_kernel(
    const float* __restrict__ x,
    const float* __restrict__ W1, const float* __restrict__ W2,
    const float* __restrict__ lw1)
{
    int gid = blockIdx.x * 256 + threadIdx.x;

    // zero degree counters + ticket
    if (gid < NN) g_deg[gid] = 0;
    if (gid == NN) g_ticket = 0;

    // weight splits (28672 elements total)
    const int N1 = HID * FIN, N2 = HID * HID, N3 = FILT * HID;
    if (gid < N1) {
        split2(W1[gid], g_w1h[gid], g_w1l[gid]);
    } else if (gid < N1 + N2) {
        int j = gid - N1;
        split2(W2[j], g_w2h[j], g_w2l[j]);
    } else if (gid < N1 + N2 + N3) {
        int j = gid - N1 - N2;
        split2(lw1[j], g_w3h[j], g_w3l[j]);
    }

    // x split + permute: dest row m = t*NN + n  <-  x[n][t][:]
    int w = blockIdx.x * 8 + (threadIdx.x >> 5);   // grid sized to MROWS/8
    int lane = threadIdx.x & 31;
    int t = w / NN, n = w - t * NN;
    float2 v = *(const float2*)(x + ((size_t)n * TT + t) * FIN + lane * 2);
    __nv_bfloat162 h2, l2;
    split2(v.x, h2.x, l2.x);
    split2(v.y, h2.y, l2.y);
    *(__nv_bfloat162*)(g_xh + (size_t)w * FIN + lane * 2) = h2;
    *(__nv_bfloat162*)(g_xl + (size_t)w * FIN + lane * 2) = l2;
}

// ---------------- CSR build: count + scan (fused, last-block scans) --------
__global__ __launch_bounds__(1024) void count_scan_kernel(const int* __restrict__ ei) {
    int idx = blockIdx.x * 1024 + threadIdx.x;
    if (idx < ETOT) {
        int dst = (idx < EE) ? ei[EE + idx] : (idx - EE);
        atomicAdd(&g_deg[dst], 1);
    }
    __threadfence();
    __shared__ bool last;
    if (threadIdx.x == 0)
        last = (atomicAdd(&g_ticket, 1) == (int)gridDim.x - 1);
    __syncthreads();
    if (!last) return;

    __shared__ int sh[1024];
    __shared__ int carry;
    if (threadIdx.x == 0) carry = 0;
    __syncthreads();
    for (int base = 0; base < NN; base += 1024) {
        int i = base + threadIdx.x;
        int v = (i < NN) ? g_deg[i] : 0;
        sh[threadIdx.x] = v;
        __syncthreads();
        for (int off = 1; off < 1024; off <<= 1) {
            int t = (threadIdx.x >= off) ? sh[threadIdx.x - off] : 0;
            __syncthreads();
            sh[threadIdx.x] += t;
            __syncthreads();
        }
        int excl = sh[threadIdx.x] - v + carry;
        if (i < NN) { g_rowptr[i] = excl; g_cursor[i] = excl; }
        __syncthreads();
        if (threadIdx.x == 1023) carry += sh[1023];
        __syncthreads();
    }
    if (threadIdx.x == 0) g_rowptr[NN] = ETOT;
}

__global__ void scatter_kernel(const int* __restrict__ ei) {
    int idx = blockIdx.x * blockDim.x + threadIdx.x;
    if (idx >= ETOT) return;
    int src = (idx < EE) ? ei[idx] : (idx - EE);
    int dst = (idx < EE) ? ei[EE + idx] : (idx - EE);
    int p = atomicAdd(&g_cursor[dst], 1);
    g_csrc[p] = src;
}

// ---------------- bf16x3 tensor-core GEMM (ldmatrix fragments) -------------
// C[M x BN] = A[M x K] * B[BN x K]^T, A/B given as bf16 hi/lo planes.
// ESED: emit per-row per-head attention scores es/ed + store C (fp16).
// FINAL: relu(bias+C) dot lw2 + lb2 -> fout, no C store.

#define MMA_BF16(d, a0, a1, a2, a3, b0, b1)                                  \
    asm volatile(                                                            \
        "mma.sync.aligned.m16n8k16.row.col.f32.bf16.bf16.f32 "               \
        "{%0,%1,%2,%3}, {%4,%5,%6,%7}, {%8,%9}, {%0,%1,%2,%3};"              \
        : "+f"(d[0]), "+f"(d[1]), "+f"(d[2]), "+f"(d[3])                     \
        : "r"(a0), "r"(a1), "r"(a2), "r"(a3), "r"(b0), "r"(b1))

#define LDSM_X4(r0, r1, r2, r3, addr)                                        \
    asm volatile(                                                            \
        "ldmatrix.sync.aligned.m8n8.x4.shared.b16 {%0,%1,%2,%3}, [%4];"      \
        : "=r"(r0), "=r"(r1), "=r"(r2), "=r"(r3) : "r"(addr))

template<int BN, int ESED, int FINAL>
__global__ __launch_bounds__(256) void mma_gemm(
    const __nv_bfloat16* __restrict__ Ah, const __nv_bfloat16* __restrict__ Al,
    const __nv_bfloat16* __restrict__ Bh, const __nv_bfloat16* __restrict__ Bl,
    __half* __restrict__ Ch, const float* __restrict__ bias,
    const float* __restrict__ attS, const float* __restrict__ attD,
    const float* __restrict__ lw2, const float* __restrict__ lb2,
    float* __restrict__ fout, int K)
{
    const int BK = 32;
    const int LDK = BK + 8;
    const int BNT = BN / 16;
    __shared__ __nv_bfloat16 AsH[128][LDK], AsL[128][LDK];
    __shared__ __nv_bfloat16 BsH[BN][LDK],  BsL[BN][LDK];
    __shared__ float shp[128];

    int tid = threadIdx.x;
    int lane = tid & 31, w = tid >> 5;
    int wm = w >> 1, wn = w & 1;
    int m0 = blockIdx.x * 128;
    int g = lane >> 2, c = lane & 3;

    // ldmatrix lane addressing
    int a_row = wm * 32 + (lane & 15);           // + mt*16
    int a_col = ((lane >> 4) << 3);              // + kb
    int b_row = wn * (BN / 2) + ((lane >> 4) << 3) + (lane & 7);  // + np*16
    int b_col = (((lane >> 3) & 1) << 3);        // + kb

    if (FINAL && tid < 128) shp[tid] = 0.f;

    float acc[2][BNT][4];
#pragma unroll
    for (int i = 0; i < 2; i++)
#pragma unroll
        for (int j = 0; j < BNT; j++)
#pragma unroll
            for (int q = 0; q < 4; q++) acc[i][j][q] = 0.f;

    for (int k0 = 0; k0 < K; k0 += BK) {
        // A tile copy: 128 x 32 bf16 per plane, as uint4 (8 elts)
#pragma unroll
        for (int q = tid; q < 128 * BK / 8; q += 256) {
            int r = q >> 2, kq = (q & 3) * 8;
            size_t off = (size_t)(m0 + r) * K + k0 + kq;
            *(uint4*)&AsH[r][kq] = *(const uint4*)(Ah + off);
            *(uint4*)&AsL[r][kq] = *(const uint4*)(Al + off);
        }
        // B tile copy
        for (int q = tid; q < BN * BK / 8; q += 256) {
            int r = q >> 2, kq = (q & 3) * 8;
            size_t off = (size_t)r * K + k0 + kq;
            *(uint4*)&BsH[r][kq] = *(const uint4*)(Bh + off);
            *(uint4*)&BsL[r][kq] = *(const uint4*)(Bl + off);
        }
        __syncthreads();

#pragma unroll
        for (int ks = 0; ks < BK / 16; ks++) {
            int kb = ks * 16;
            uint32_t aH[2][4], aL[2][4];
#pragma unroll
            for (int mt = 0; mt < 2; mt++) {
                uint32_t adH = (uint32_t)__cvta_generic_to_shared(
                    &AsH[a_row + mt * 16][kb + a_col]);
                LDSM_X4(aH[mt][0], aH[mt][1], aH[mt][2], aH[mt][3], adH);
                uint32_t adL = (uint32_t)__cvta_generic_to_shared(
                    &AsL[a_row + mt * 16][kb + a_col]);
                LDSM_X4(aL[mt][0], aL[mt][1], aL[mt][2], aL[mt][3], adL);
            }
            uint32_t bH[BNT][2], bL[BNT][2];
#pragma unroll
            for (int np = 0; np < BNT / 2; np++) {
                uint32_t adH = (uint32_t)__cvta_generic_to_shared(
                    &BsH[b_row + np * 16][kb + b_col]);
                LDSM_X4(bH[2 * np][0], bH[2 * np][1], bH[2 * np + 1][0], bH[2 * np + 1][1], adH);
                uint32_t adL = (uint32_t)__cvta_generic_to_shared(
                    &BsL[b_row + np * 16][kb + b_col]);
                LDSM_X4(bL[2 * np][0], bL[2 * np][1], bL[2 * np + 1][0], bL[2 * np + 1][1], adL);
            }
#pragma unroll
            for (int nt = 0; nt < BNT; nt++) {
#pragma unroll
                for (int mt = 0; mt < 2; mt++) {
                    MMA_BF16(acc[mt][nt], aH[mt][0], aH[mt][1], aH[mt][2], aH[mt][3],
                             bH[nt][0], bH[nt][1]);
                    MMA_BF16(acc[mt][nt], aH[mt][0], aH[mt][1], aH[mt][2], aH[mt][3],
                             bL[nt][0], bL[nt][1]);
                    MMA_BF16(acc[mt][nt], aL[mt][0], aL[mt][1], aL[mt][2], aL[mt][3],
                             bH[nt][0], bH[nt][1]);
                }
            }
        }
        __syncthreads();
    }

    if constexpr (FINAL) {
        float l2v[BNT][2], bv[BNT][2];
#pragma unroll
        for (int nt = 0; nt < BNT; nt++) {
            int c0 = wn * (BN / 2) + nt * 8 + 2 * c;
            l2v[nt][0] = lw2[c0];  l2v[nt][1] = lw2[c0 + 1];
            bv[nt][0]  = bias[c0]; bv[nt][1]  = bias[c0 + 1];
        }
#pragma unroll
        for (int mt = 0; mt < 2; mt++) {
#pragma unroll
            for (int rh = 0; rh < 2; rh++) {
                float p = 0.f;
#pragma unroll
                for (int nt = 0; nt < BNT; nt++) {
                    float v0 = fmaxf(acc[mt][nt][2 * rh]     + bv[nt][0], 0.f);
                    float v1 = fmaxf(acc[mt][nt][2 * rh + 1] + bv[nt][1], 0.f);
                    p += v0 * l2v[nt][0] + v1 * l2v[nt][1];
                }
                p += __shfl_xor_sync(0xffffffffu, p, 1);
                p += __shfl_xor_sync(0xffffffffu, p, 2);
                if (c == 0)
                    atomicAdd(&shp[wm * 32 + mt * 16 + g + 8 * rh], p);
            }
        }
        __syncthreads();
        if (tid < 128) fout[m0 + tid] = shp[tid] + lb2[0];
        return;
    }

    if constexpr (ESED) {
        float aS[8][2], aD[8][2];
#pragma unroll
        for (int nt = 0; nt < 8; nt++) {
            int c0 = wn * 64 + nt * 8 + 2 * c;
            aS[nt][0] = attS[c0]; aS[nt][1] = attS[c0 + 1];
            aD[nt][0] = attD[c0]; aD[nt][1] = attD[c0 + 1];
        }
#pragma unroll
        for (int mt = 0; mt < 2; mt++) {
#pragma unroll
            for (int rh = 0; rh < 2; rh++) {
                float es0 = 0.f, es1 = 0.f, ed0 = 0.f, ed1 = 0.f;
#pragma unroll
                for (int nt = 0; nt < 8; nt++) {
                    float v0 = acc[mt][nt][2 * rh], v1 = acc[mt][nt][2 * rh + 1];
                    float cs = v0 * aS[nt][0] + v1 * aS[nt][1];
                    float cd = v0 * aD[nt][0] + v1 * aD[nt][1];
                    if (nt < 4) { es0 += cs; ed0 += cd; }
                    else        { es1 += cs; ed1 += cd; }
                }
                es0 += __shfl_xor_sync(0xffffffffu, es0, 1);
                es0 += __shfl_xor_sync(0xffffffffu, es0, 2);
                es1 += __shfl_xor_sync(0xffffffffu, es1, 1);
                es1 += __shfl_xor_sync(0xffffffffu, es1, 2);
                ed0 += __shfl_xor_sync(0xffffffffu, ed0, 1);
                ed0 += __shfl_xor_sync(0xffffffffu, ed0, 2);
                ed1 += __shfl_xor_sync(0xffffffffu, ed1, 1);
                ed1 += __shfl_xor_sync(0xffffffffu, ed1, 2);
                if (c == 0) {
                    int row = m0 + wm * 32 + mt * 16 + g + 8 * rh;
                    *(float2*)&g_es[(size_t)row * 4 + 2 * wn] = make_float2(es0, es1);
                    *(float2*)&g_ed[(size_t)row * 4 + 2 * wn] = make_float2(ed0, ed1);
                }
            }
        }
    }

    // C store (fp16) for gather
#pragma unroll
    for (int mt = 0; mt < 2; mt++) {
        int r0 = m0 + wm * 32 + mt * 16 + g;
#pragma unroll
        for (int nt = 0; nt < BNT; nt++) {
            int col = wn * (BN / 2) + nt * 8 + 2 * c;
            *(__half2*)(Ch + (size_t)r0 * BN + col) =
                __floats2half2_rn(acc[mt][nt][0], acc[mt][nt][1]);
            *(__half2*)(Ch + (size_t)(r0 + 8) * BN + col) =
                __floats2half2_rn(acc[mt][nt][2], acc[mt][nt][3]);
        }
    }
}

// ---------------- aggregation: smem-mediated packed softmax ----------------
// one warp per (t, dst). Phase A: lane=(edge_in_chunk*4+head), one exp per
// edge-head; every lane stores its {w, src} pair (8B, one STS.64).
// Phase B: lane owns 4 features (head=lane>>3); per edge one LDS.64 fetches
// {w, src} together; padded slots have w=0 and a clamped src row.
__global__ __launch_bounds__(256) void agg_kernel(
    const __half* __restrict__ h, const float* __restrict__ bias,
    __nv_bfloat16* __restrict__ outH, __nv_bfloat16* __restrict__ outL)
{
    __shared__ float2 sw[8][2][32];
    int ws = threadIdx.x >> 5;
    int w = blockIdx.x * 8 + ws;
    if (w >= MROWS) return;
    int lane = threadIdx.x & 31;
    int he = lane & 3, eo = lane >> 2;
    int hf = lane >> 3;
    int t = w / NN, d = w - t * NN;
    int beg = g_rowptr[d], end = g_rowptr[d + 1];
    float edv = g_ed[(size_t)w * 4 + he];
    const __half* ht  = h + (size_t)t * NN * HID;
    const __half* htl = ht + lane * 4;
    const float* est = g_es + (size_t)t * NN * 4;

    float s = 0.f;
    float4 acc = make_float4(0.f, 0.f, 0.f, 0.f);
    int pb = 0;
    for (int base = beg; base < end; base += 8, pb ^= 1) {
        int e = base + eo;
        int ec = min(e, end - 1);
        int src = __ldg(&g_csrc[ec]);
        float ev = __ldg(&est[src * 4 + he]) + edv;
        ev = fmaxf(ev, 0.2f * ev);                    // leaky_relu(0.2)
        float wv = (e < end) ? __expf(ev) : 0.f;
        s += wv;
        sw[ws][pb][lane] = make_float2(wv, __int_as_float(src));
        __syncwarp();
        int nE = end - base;
#pragma unroll
        for (int j = 0; j < 4; j++) {
            float2 p = sw[ws][pb][j * 4 + hf];
            uint2 hp = *(const uint2*)(htl + (__float_as_int(p.y) << 7));
            float2 f01 = __half22float2(*(__half2*)&hp.x);
            float2 f23 = __half22float2(*(__half2*)&hp.y);
            acc.x += p.x * f01.x; acc.y += p.x * f01.y;
            acc.z += p.x * f23.x; acc.w += p.x * f23.y;
        }
        if (nE > 4) {
#pragma unroll
            for (int j = 4; j < 8; j++) {
                float2 p = sw[ws][pb][j * 4 + hf];
                uint2 hp = *(const uint2*)(htl + (__float_as_int(p.y) << 7));
                float2 f01 = __half22float2(*(__half2*)&hp.x);
                float2 f23 = __half22float2(*(__half2*)&hp.y);
                acc.x += p.x * f01.x; acc.y += p.x * f01.y;
                acc.z += p.x * f23.x; acc.w += p.x * f23.y;
            }
        }
    }
    s += __shfl_xor_sync(0xffffffffu, s, 4);
    s += __shfl_xor_sync(0xffffffffu, s, 8);
    s += __shfl_xor_sync(0xffffffffu, s, 16);
    float sAll = __shfl_sync(0xffffffffu, s, hf);

    float inv = 1.f / (sAll + 1e-16f);
    float4 b4 = *(const float4*)(bias + lane * 4);
    float ox = acc.x * inv + b4.x;
    float oy = acc.y * inv + b4.y;
    float oz = acc.z * inv + b4.z;
    float ow = acc.w * inv + b4.w;
    ox = ox > 0.f ? ox : (__expf(ox) - 1.f);
    oy = oy > 0.f ? oy : (__expf(oy) - 1.f);
    oz = oz > 0.f ? oz : (__expf(oz) - 1.f);
    ow = ow > 0.f ? ow : (__expf(ow) - 1.f);

    __nv_bfloat162 h01, h23, l01, l23;
    split2(ox, h01.x, l01.x);
    split2(oy, h01.y, l01.y);
    split2(oz, h23.x, l23.x);
    split2(ow, h23.y, l23.y);
    size_t off = (size_t)w * HID + lane * 4;
    *(__nv_bfloat162*)(outH + off)     = h01;
    *(__nv_bfloat162*)(outH + off + 2) = h23;
    *(__nv_bfloat162*)(outL + off)     = l01;
    *(__nv_bfloat162*)(outL + off + 2) = l23;
}

// ---------------- launch ----------------
extern "C" void kernel_launch(void* const* d_in, const int* in_sizes, int n_in,
                              void* d_out, int out_size) {
    const float* x        = (const float*)d_in[0];
    const int*   ei       = (const int*)d_in[1];
    const float* W1       = (const float*)d_in[2];
    const float* att_src1 = (const float*)d_in[3];
    const float* att_dst1 = (const float*)d_in[4];
    const float* b1       = (const float*)d_in[5];
    const float* W2       = (const float*)d_in[6];
    const float* att_src2 = (const float*)d_in[7];
    const float* att_dst2 = (const float*)d_in[8];
    const float* b2       = (const float*)d_in[9];
    const float* lw1      = (const float*)d_in[10];
    const float* lb1      = (const float*)d_in[11];
    const float* lw2      = (const float*)d_in[12];
    const float* lb2      = (const float*)d_in[13];
    float* out = (float*)d_out;

    __half* h16 = nullptr;
    __nv_bfloat16 *ah = nullptr, *al = nullptr, *xh = nullptr, *xl = nullptr;
    __nv_bfloat16 *w1h = nullptr, *w1l = nullptr, *w2h = nullptr, *w2l = nullptr;
    __nv_bfloat16 *w3h = nullptr, *w3l = nullptr;
    cudaGetSymbolAddress((void**)&h16, g_h16);
    cudaGetSymbolAddress((void**)&ah,  g_ah);
    cudaGetSymbolAddress((void**)&al,  g_al);
    cudaGetSymbolAddress((void**)&xh,  g_xh);
    cudaGetSymbolAddress((void**)&xl,  g_xl);
    cudaGetSymbolAddress((void**)&w1h, g_w1h);
    cudaGetSymbolAddress((void**)&w1l, g_w1l);
    cudaGetSymbolAddress((void**)&w2h, g_w2h);
    cudaGetSymbolAddress((void**)&w2l, g_w2l);
    cudaGetSymbolAddress((void**)&w3h, g_w3h);
    cudaGetSymbolAddress((void**)&w3l, g_w3l);

    // #1 prep: zero deg/ticket + weight split + x split/permute
    prep_kernel<<<MROWS / 8, 256>>>(x, W1, W2, lw1);
    // #2, #3 CSR build
    count_scan_kernel<<<(ETOT + 1023) / 1024, 1024>>>(ei);
    scatter_kernel<<<(ETOT + 255) / 256, 256>>>(ei);

    dim3 gg(MROWS / 128);

    // #4 layer-1 GEMM (+es/ed), #5 agg
    mma_gemm<128, 1, 0><<<gg, 256>>>(xh, xl, w1h, w1l, h16, nullptr,
                                     att_src1, att_dst1, nullptr, nullptr,
                                     nullptr, FIN);
    agg_kernel<<<MROWS / 8, 256>>>(h16, b1, ah, al);

    // #6 layer-2 GEMM (profiled by ncu -s 5 -c 1), #7 agg
    mma_gemm<128, 1, 0><<<gg, 256>>>(ah, al, w2h, w2l, h16, nullptr,
                                     att_src2, att_dst2, nullptr, nullptr,
                                     nullptr, HID);
    agg_kernel<<<MROWS / 8, 256>>>(h16, b2, ah, al);

    // #8 MLP head + final dot (fully fused)
    mma_gemm<32, 0, 1><<<gg, 256>>>(ah, al, w3h, w3l, nullptr, lb1,
                                    nullptr, nullptr, lw2, lb2,
                                    out, HID);
}

// round 6
// speedup vs baseline: 1.2273x; 1.2273x over previous
#include <cuda_runtime.h>
#include <cuda_bf16.h>
#include <cuda_fp16.h>
#include <cstdint>

// Problem constants
#define NN 20000
#define TT 8
#define FIN 64
#define HEADS 4
#define FILT 32
#define HID 128
#define EE 320000
#define ETOT 340000      // E + N self loops
#define MROWS 160000     // N*T

// ---------------- device scratch ----------------
__device__ __half g_h16[(size_t)MROWS * HID];  // post-GEMM h (fp16, gather source)
__device__ __half g_a16[(size_t)MROWS * HID];  // agg output (fp16, next GEMM A)
__device__ __half g_x16[(size_t)MROWS * FIN];  // x (fp16, permuted)
__device__ __half g_w1[HID * FIN];
__device__ __half g_w2[HID * HID];
__device__ __half g_w3[FILT * HID];
__device__ float  g_es[(size_t)MROWS * HEADS];
__device__ float  g_ed[(size_t)MROWS * HEADS];
__device__ int    g_deg[NN];
__device__ int    g_ticket;
__device__ int    g_rowptr[NN + 1];
__device__ int    g_cursor[NN];
__device__ int    g_csrc[ETOT];

// ---------------- prep: zero deg/ticket + fp16 weights + fp16/permute x ----
__global__ __launch_bounds__(256) void prep_kernel(
    const float* __restrict__ x,
    const float* __restrict__ W1, const float* __restrict__ W2,
    const float* __restrict__ lw1)
{
    int gid = blockIdx.x * 256 + threadIdx.x;

    if (gid < NN) g_deg[gid] = 0;
    if (gid == NN) g_ticket = 0;

    const int N1 = HID * FIN, N2 = HID * HID, N3 = FILT * HID;
    if (gid < N1) {
        g_w1[gid] = __float2half_rn(W1[gid]);
    } else if (gid < N1 + N2) {
        int j = gid - N1;
        g_w2[j] = __float2half_rn(W2[j]);
    } else if (gid < N1 + N2 + N3) {
        int j = gid - N1 - N2;
        g_w3[j] = __float2half_rn(lw1[j]);
    }

    // x convert + permute: dest row m = t*NN + n  <-  x[n][t][:]
    int w = blockIdx.x * 8 + (threadIdx.x >> 5);   // grid sized to MROWS/8
    int lane = threadIdx.x & 31;
    int t = w / NN, n = w - t * NN;
    float2 v = *(const float2*)(x + ((size_t)n * TT + t) * FIN + lane * 2);
    *(__half2*)(g_x16 + (size_t)w * FIN + lane * 2) = __floats2half2_rn(v.x, v.y);
}

// ---------------- CSR build: count + scan (fused, last-block scans) --------
__global__ __launch_bounds__(1024) void count_scan_kernel(const int* __restrict__ ei) {
    int idx = blockIdx.x * 1024 + threadIdx.x;
    if (idx < ETOT) {
        int dst = (idx < EE) ? ei[EE + idx] : (idx - EE);
        atomicAdd(&g_deg[dst], 1);
    }
    __threadfence();
    __shared__ bool last;
    if (threadIdx.x == 0)
        last = (atomicAdd(&g_ticket, 1) == (int)gridDim.x - 1);
    __syncthreads();
    if (!last) return;

    __shared__ int sh[1024];
    __shared__ int carry;
    if (threadIdx.x == 0) carry = 0;
    __syncthreads();
    for (int base = 0; base < NN; base += 1024) {
        int i = base + threadIdx.x;
        int v = (i < NN) ? g_deg[i] : 0;
        sh[threadIdx.x] = v;
        __syncthreads();
        for (int off = 1; off < 1024; off <<= 1) {
            int t = (threadIdx.x >= off) ? sh[threadIdx.x - off] : 0;
            __syncthreads();
            sh[threadIdx.x] += t;
            __syncthreads();
        }
        int excl = sh[threadIdx.x] - v + carry;
        if (i < NN) { g_rowptr[i] = excl; g_cursor[i] = excl; }
        __syncthreads();
        if (threadIdx.x == 1023) carry += sh[1023];
        __syncthreads();
    }
    if (threadIdx.x == 0) g_rowptr[NN] = ETOT;
}

__global__ void scatter_kernel(const int* __restrict__ ei) {
    int idx = blockIdx.x * blockDim.x + threadIdx.x;
    if (idx >= ETOT) return;
    int src = (idx < EE) ? ei[idx] : (idx - EE);
    int dst = (idx < EE) ? ei[EE + idx] : (idx - EE);
    int p = atomicAdd(&g_cursor[dst], 1);
    g_csrc[p] = src;
}

// ---------------- fp16 tensor-core GEMM, cp.async 2-stage pipeline ---------
// C[M x BN] = A[M x K] * B[BN x K]^T, fp16 in, fp32 accumulate.
// ESED: emit per-row per-head attention scores es/ed + store C (fp16).
// FINAL: relu(bias+C) dot lw2 + lb2 -> fout, no C store.

#define MMA_F16(d, a0, a1, a2, a3, b0, b1)                                   \
    asm volatile(                                                            \
        "mma.sync.aligned.m16n8k16.row.col.f32.f16.f16.f32 "                 \
        "{%0,%1,%2,%3}, {%4,%5,%6,%7}, {%8,%9}, {%0,%1,%2,%3};"              \
        : "+f"(d[0]), "+f"(d[1]), "+f"(d[2]), "+f"(d[3])                     \
        : "r"(a0), "r"(a1), "r"(a2), "r"(a3), "r"(b0), "r"(b1))

#define LDSM_X4(r0, r1, r2, r3, addr)                                        \
    asm volatile(                                                            \
        "ldmatrix.sync.aligned.m8n8.x4.shared.b16 {%0,%1,%2,%3}, [%4];"      \
        : "=r"(r0), "=r"(r1), "=r"(r2), "=r"(r3) : "r"(addr))

__device__ __forceinline__ void cpa16(void* s, const void* g) {
    uint32_t sa = (uint32_t)__cvta_generic_to_shared(s);
    asm volatile("cp.async.ca.shared.global [%0], [%1], 16;" :: "r"(sa), "l"(g));
}

template<int BN, int ESED, int FINAL>
__global__ __launch_bounds__(256) void mma_gemm(
    const __half* __restrict__ A, const __half* __restrict__ B,
    __half* __restrict__ Ch, const float* __restrict__ bias,
    const float* __restrict__ attS, const float* __restrict__ attD,
    const float* __restrict__ lw2, const float* __restrict__ lb2,
    float* __restrict__ fout, int K)
{
    const int BK = 32;
    const int LDK = BK + 8;   // pad: conflict-free ldmatrix
    const int BNT = BN / 16;
    __shared__ __half As[2][128][LDK];
    __shared__ __half Bs[2][BN][LDK];
    __shared__ float shp[128];

    int tid = threadIdx.x;
    int lane = tid & 31, w = tid >> 5;
    int wm = w >> 1, wn = w & 1;
    int m0 = blockIdx.x * 128;
    int g = lane >> 2, c = lane & 3;

    // ldmatrix lane addressing
    int a_row = wm * 32 + (lane & 15);                           // + mt*16
    int a_col = ((lane >> 4) << 3);                              // + kb
    int b_row = wn * (BN / 2) + ((lane >> 4) << 3) + (lane & 7); // + np*16
    int b_col = (((lane >> 3) & 1) << 3);                        // + kb

    if (FINAL && tid < 128) shp[tid] = 0.f;

    float acc[2][BNT][4];
#pragma unroll
    for (int i = 0; i < 2; i++)
#pragma unroll
        for (int j = 0; j < BNT; j++)
#pragma unroll
            for (int q = 0; q < 4; q++) acc[i][j][q] = 0.f;

    auto load_stage = [&](int st, int k0) {
#pragma unroll
        for (int q = tid; q < 128 * BK / 8; q += 256) {
            int r = q >> 2, kq = (q & 3) * 8;
            cpa16(&As[st][r][kq], A + (size_t)(m0 + r) * K + k0 + kq);
        }
#pragma unroll
        for (int q = tid; q < BN * BK / 8; q += 256) {
            int r = q >> 2, kq = (q & 3) * 8;
            cpa16(&Bs[st][r][kq], B + (size_t)r * K + k0 + kq);
        }
        asm volatile("cp.async.commit_group;");
    };

    int nk = K / BK;
    load_stage(0, 0);

    for (int kt = 0; kt < nk; kt++) {
        int st = kt & 1;
        if (kt + 1 < nk) {
            load_stage(st ^ 1, (kt + 1) * BK);
            asm volatile("cp.async.wait_group 1;");
        } else {
            asm volatile("cp.async.wait_group 0;");
        }
        __syncthreads();

#pragma unroll
        for (int ks = 0; ks < BK / 16; ks++) {
            int kb = ks * 16;
            uint32_t a[2][4];
#pragma unroll
            for (int mt = 0; mt < 2; mt++) {
                uint32_t ad = (uint32_t)__cvta_generic_to_shared(
                    &As[st][a_row + mt * 16][kb + a_col]);
                LDSM_X4(a[mt][0], a[mt][1], a[mt][2], a[mt][3], ad);
            }
            uint32_t b[BNT][2];
#pragma unroll
            for (int np = 0; np < BNT / 2; np++) {
                uint32_t bd = (uint32_t)__cvta_generic_to_shared(
                    &Bs[st][b_row + np * 16][kb + b_col]);
                LDSM_X4(b[2 * np][0], b[2 * np][1], b[2 * np + 1][0], b[2 * np + 1][1], bd);
            }
#pragma unroll
            for (int nt = 0; nt < BNT; nt++)
#pragma unroll
                for (int mt = 0; mt < 2; mt++)
                    MMA_F16(acc[mt][nt], a[mt][0], a[mt][1], a[mt][2], a[mt][3],
                            b[nt][0], b[nt][1]);
        }
        __syncthreads();
    }

    if constexpr (FINAL) {
        float l2v[BNT][2], bv[BNT][2];
#pragma unroll
        for (int nt = 0; nt < BNT; nt++) {
            int c0 = wn * (BN / 2) + nt * 8 + 2 * c;
            l2v[nt][0] = lw2[c0];  l2v[nt][1] = lw2[c0 + 1];
            bv[nt][0]  = bias[c0]; bv[nt][1]  = bias[c0 + 1];
        }
#pragma unroll
        for (int mt = 0; mt < 2; mt++) {
#pragma unroll
            for (int rh = 0; rh < 2; rh++) {
                float p = 0.f;
#pragma unroll
                for (int nt = 0; nt < BNT; nt++) {
                    float v0 = fmaxf(acc[mt][nt][2 * rh]     + bv[nt][0], 0.f);
                    float v1 = fmaxf(acc[mt][nt][2 * rh + 1] + bv[nt][1], 0.f);
                    p += v0 * l2v[nt][0] + v1 * l2v[nt][1];
                }
                p += __shfl_xor_sync(0xffffffffu, p, 1);
                p += __shfl_xor_sync(0xffffffffu, p, 2);
                if (c == 0)
                    atomicAdd(&shp[wm * 32 + mt * 16 + g + 8 * rh], p);
            }
        }
        __syncthreads();
        if (tid < 128) fout[m0 + tid] = shp[tid] + lb2[0];
        return;
    }

    if constexpr (ESED) {
        float aS[8][2], aD[8][2];
#pragma unroll
        for (int nt = 0; nt < 8; nt++) {
            int c0 = wn * 64 + nt * 8 + 2 * c;
            aS[nt][0] = attS[c0]; aS[nt][1] = attS[c0 + 1];
            aD[nt][0] = attD[c0]; aD[nt][1] = attD[c0 + 1];
        }
#pragma unroll
        for (int mt = 0; mt < 2; mt++) {
#pragma unroll
            for (int rh = 0; rh < 2; rh++) {
                float es0 = 0.f, es1 = 0.f, ed0 = 0.f, ed1 = 0.f;
#pragma unroll
                for (int nt = 0; nt < 8; nt++) {
                    float v0 = acc[mt][nt][2 * rh], v1 = acc[mt][nt][2 * rh + 1];
                    float cs = v0 * aS[nt][0] + v1 * aS[nt][1];
                    float cd = v0 * aD[nt][0] + v1 * aD[nt][1];
                    if (nt < 4) { es0 += cs; ed0 += cd; }
                    else        { es1 += cs; ed1 += cd; }
                }
                es0 += __shfl_xor_sync(0xffffffffu, es0, 1);
                es0 += __shfl_xor_sync(0xffffffffu, es0, 2);
                es1 += __shfl_xor_sync(0xffffffffu, es1, 1);
                es1 += __shfl_xor_sync(0xffffffffu, es1, 2);
                ed0 += __shfl_xor_sync(0xffffffffu, ed0, 1);
                ed0 += __shfl_xor_sync(0xffffffffu, ed0, 2);
                ed1 += __shfl_xor_sync(0xffffffffu, ed1, 1);
                ed1 += __shfl_xor_sync(0xffffffffu, ed1, 2);
                if (c == 0) {
                    int row = m0 + wm * 32 + mt * 16 + g + 8 * rh;
                    *(float2*)&g_es[(size_t)row * 4 + 2 * wn] = make_float2(es0, es1);
                    *(float2*)&g_ed[(size_t)row * 4 + 2 * wn] = make_float2(ed0, ed1);
                }
            }
        }
    }

    // C store (fp16) for gather
#pragma unroll
    for (int mt = 0; mt < 2; mt++) {
        int r0 = m0 + wm * 32 + mt * 16 + g;
#pragma unroll
        for (int nt = 0; nt < BNT; nt++) {
            int col = wn * (BN / 2) + nt * 8 + 2 * c;
            *(__half2*)(Ch + (size_t)r0 * BN + col) =
                __floats2half2_rn(acc[mt][nt][0], acc[mt][nt][1]);
            *(__half2*)(Ch + (size_t)(r0 + 8) * BN + col) =
                __floats2half2_rn(acc[mt][nt][2], acc[mt][nt][3]);
        }
    }
}

// ---------------- aggregation: smem-mediated packed softmax ----------------
// one warp per (t, dst). Phase A: lane=(edge_in_chunk*4+head), one exp per
// edge-head; every lane stores its {w, src} pair (8B, one STS.64).
// Phase B: lane owns 4 features (head=lane>>3); per edge one LDS.64 fetches
// {w, src} together; padded slots have w=0 and a clamped src row.
__global__ __launch_bounds__(256) void agg_kernel(
    const __half* __restrict__ h, const float* __restrict__ bias,
    __half* __restrict__ out16)
{
    __shared__ float2 sw[8][2][32];
    int ws = threadIdx.x >> 5;
    int w = blockIdx.x * 8 + ws;
    if (w >= MROWS) return;
    int lane = threadIdx.x & 31;
    int he = lane & 3, eo = lane >> 2;
    int hf = lane >> 3;
    int t = w / NN, d = w - t * NN;
    int beg = g_rowptr[d], end = g_rowptr[d + 1];
    float edv = g_ed[(size_t)w * 4 + he];
    const __half* ht  = h + (size_t)t * NN * HID;
    const __half* htl = ht + lane * 4;
    const float* est = g_es + (size_t)t * NN * 4;

    float s = 0.f;
    float4 acc = make_float4(0.f, 0.f, 0.f, 0.f);
    int pb = 0;
    for (int base = beg; base < end; base += 8, pb ^= 1) {
        int e = base + eo;
        int ec = min(e, end - 1);
        int src = __ldg(&g_csrc[ec]);
        float ev = __ldg(&est[src * 4 + he]) + edv;
        ev = fmaxf(ev, 0.2f * ev);                    // leaky_relu(0.2)
        float wv = (e < end) ? __expf(ev) : 0.f;
        s += wv;
        sw[ws][pb][lane] = make_float2(wv, __int_as_float(src));
        __syncwarp();
        int nE = end - base;
#pragma unroll
        for (int j = 0; j < 4; j++) {
            float2 p = sw[ws][pb][j * 4 + hf];
            uint2 hp = *(const uint2*)(htl + (__float_as_int(p.y) << 7));
            float2 f01 = __half22float2(*(__half2*)&hp.x);
            float2 f23 = __half22float2(*(__half2*)&hp.y);
            acc.x += p.x * f01.x; acc.y += p.x * f01.y;
            acc.z += p.x * f23.x; acc.w += p.x * f23.y;
        }
        if (nE > 4) {
#pragma unroll
            for (int j = 4; j < 8; j++) {
                float2 p = sw[ws][pb][j * 4 + hf];
                uint2 hp = *(const uint2*)(htl + (__float_as_int(p.y) << 7));
                float2 f01 = __half22float2(*(__half2*)&hp.x);
                float2 f23 = __half22float2(*(__half2*)&hp.y);
                acc.x += p.x * f01.x; acc.y += p.x * f01.y;
                acc.z += p.x * f23.x; acc.w += p.x * f23.y;
            }
        }
    }
    s += __shfl_xor_sync(0xffffffffu, s, 4);
    s += __shfl_xor_sync(0xffffffffu, s, 8);
    s += __shfl_xor_sync(0xffffffffu, s, 16);
    float sAll = __shfl_sync(0xffffffffu, s, hf);

    float inv = 1.f / (sAll + 1e-16f);
    float4 b4 = *(const float4*)(bias + lane * 4);
    float ox = acc.x * inv + b4.x;
    float oy = acc.y * inv + b4.y;
    float oz = acc.z * inv + b4.z;
    float ow = acc.w * inv + b4.w;
    ox = ox > 0.f ? ox : (__expf(ox) - 1.f);
    oy = oy > 0.f ? oy : (__expf(oy) - 1.f);
    oz = oz > 0.f ? oz : (__expf(oz) - 1.f);
    ow = ow > 0.f ? ow : (__expf(ow) - 1.f);

    size_t off = (size_t)w * HID + lane * 4;
    *(__half2*)(out16 + off)     = __floats2half2_rn(ox, oy);
    *(__half2*)(out16 + off + 2) = __floats2half2_rn(oz, ow);
}

// ---------------- launch ----------------
extern "C" void kernel_launch(void* const* d_in, const int* in_sizes, int n_in,
                              void* d_out, int out_size) {
    const float* x        = (const float*)d_in[0];
    const int*   ei       = (const int*)d_in[1];
    const float* W1       = (const float*)d_in[2];
    const float* att_src1 = (const float*)d_in[3];
    const float* att_dst1 = (const float*)d_in[4];
    const float* b1       = (const float*)d_in[5];
    const float* W2       = (const float*)d_in[6];
    const float* att_src2 = (const float*)d_in[7];
    const float* att_dst2 = (const float*)d_in[8];
    const float* b2       = (const float*)d_in[9];
    const float* lw1      = (const float*)d_in[10];
    const float* lb1      = (const float*)d_in[11];
    const float* lw2      = (const float*)d_in[12];
    const float* lb2      = (const float*)d_in[13];
    float* out = (float*)d_out;

    __half *h16 = nullptr, *a16 = nullptr, *x16 = nullptr;
    __half *w1 = nullptr, *w2 = nullptr, *w3 = nullptr;
    cudaGetSymbolAddress((void**)&h16, g_h16);
    cudaGetSymbolAddress((void**)&a16, g_a16);
    cudaGetSymbolAddress((void**)&x16, g_x16);
    cudaGetSymbolAddress((void**)&w1,  g_w1);
    cudaGetSymbolAddress((void**)&w2,  g_w2);
    cudaGetSymbolAddress((void**)&w3,  g_w3);

    // #1 prep: zero deg/ticket + fp16 weights + fp16/permute x
    prep_kernel<<<MROWS / 8, 256>>>(x, W1, W2, lw1);
    // #2, #3 CSR build
    count_scan_kernel<<<(ETOT + 1023) / 1024, 1024>>>(ei);
    scatter_kernel<<<(ETOT + 255) / 256, 256>>>(ei);

    dim3 gg(MROWS / 128);

    // #4 layer-1 GEMM (+es/ed), #5 agg
    mma_gemm<128, 1, 0><<<gg, 256>>>(x16, w1, h16, nullptr,
                                     att_src1, att_dst1, nullptr, nullptr,
                                     nullptr, FIN);
    agg_kernel<<<MROWS / 8, 256>>>(h16, b1, a16);

    // #6 layer-2 GEMM (profiled by ncu -s 5 -c 1), #7 agg
    mma_gemm<128, 1, 0><<<gg, 256>>>(a16, w2, h16, nullptr,
                                     att_src2, att_dst2, nullptr, nullptr,
                                     nullptr, HID);
    agg_kernel<<<MROWS / 8, 256>>>(h16, b2, a16);

    // #8 MLP head + final dot (fully fused)
    mma_gemm<32, 0, 1><<<gg, 256>>>(a16, w3, nullptr, lb1,
                                    nullptr, nullptr, lw2, lb2,
                                    out, HID);
}